// round 7
// baseline (speedup 1.0000x reference)
#include <cuda_runtime.h>
#include <math.h>
#include <stdint.h>

#define L_   12
#define S_   512
#define B_   4
#define DIN_ 768
#define D_   1024
#define H_   16
#define F_   4096
#define HD_  64
#define T_   (S_*B_)   // 2048 tokens

// ---------------- scratch (static device globals; no runtime allocation) ----
__device__ float g_q[T_*D_];
__device__ float g_k[T_*D_];
__device__ float g_v[T_*D_];
__device__ float g_scores[(size_t)B_*H_*S_*S_];   // 67 MB

// split activation buffers
__device__ float g_h_hi[T_*D_],    g_h_lo[T_*D_];
__device__ float g_attn_hi[T_*D_], g_attn_lo[T_*D_];
__device__ float g_ff_hi[(size_t)T_*F_], g_ff_lo[(size_t)T_*F_];

// split weight / input buffers (filled by prep pass every call)
__device__ float g_seg_hi[T_*DIN_],  g_seg_lo[T_*DIN_];
__device__ float g_wproj_hi[DIN_*D_], g_wproj_lo[DIN_*D_];
__device__ float g_wq_hi[(size_t)L_*D_*D_], g_wq_lo[(size_t)L_*D_*D_];
__device__ float g_wk_hi[(size_t)L_*D_*D_], g_wk_lo[(size_t)L_*D_*D_];
__device__ float g_wv_hi[(size_t)L_*D_*D_], g_wv_lo[(size_t)L_*D_*D_];
__device__ float g_wo_hi[(size_t)L_*D_*D_], g_wo_lo[(size_t)L_*D_*D_];
__device__ float g_w1_hi[(size_t)L_*D_*F_], g_w1_lo[(size_t)L_*D_*F_];
__device__ float g_w2_hi[(size_t)L_*F_*D_], g_w2_lo[(size_t)L_*F_*D_];

// ---------------- tf32 helpers ---------------------------------------------
__device__ __forceinline__ unsigned f2tf32(float f) {
    unsigned u;
    asm("cvt.rna.tf32.f32 %0, %1;" : "=r"(u) : "f"(f));
    return u;
}

__device__ __forceinline__ void mma_tf32(float c[4],
    unsigned a0, unsigned a1, unsigned a2, unsigned a3,
    unsigned b0, unsigned b1)
{
    asm volatile(
        "mma.sync.aligned.m16n8k8.row.col.f32.tf32.tf32.f32 "
        "{%0,%1,%2,%3}, {%4,%5,%6,%7}, {%8,%9}, {%0,%1,%2,%3};"
        : "+f"(c[0]), "+f"(c[1]), "+f"(c[2]), "+f"(c[3])
        : "r"(a0), "r"(a1), "r"(a2), "r"(a3), "r"(b0), "r"(b1));
}

__device__ __forceinline__ void split_tf32(float f, float& hi, float& lo) {
    unsigned h = f2tf32(f);
    hi = __uint_as_float(h);
    lo = __uint_as_float(f2tf32(f - hi));
}

// ---------------- cp.async helpers -----------------------------------------
__device__ __forceinline__ void cp16(uint32_t dst, const void* src) {
    asm volatile("cp.async.cg.shared.global [%0], [%1], 16;"
                 :: "r"(dst), "l"(src) : "memory");
}
#define CP_COMMIT() asm volatile("cp.async.commit_group;" ::: "memory")
#define CP_WAIT0()  asm volatile("cp.async.wait_group 0;" ::: "memory")

// ---------------- prep: elementwise split ----------------------------------
__global__ void split_arr(const float4* __restrict__ in,
                          float4* __restrict__ hi, float4* __restrict__ lo,
                          int n4)
{
    for (int i = blockIdx.x * blockDim.x + threadIdx.x; i < n4;
         i += gridDim.x * blockDim.x) {
        float4 v = in[i];
        float4 h4, l4;
        split_tf32(v.x, h4.x, l4.x); split_tf32(v.y, h4.y, l4.y);
        split_tf32(v.z, h4.z, l4.z); split_tf32(v.w, h4.w, l4.w);
        hi[i] = h4; lo[i] = l4;
    }
}

// ---------------- tensor-core GEMM (3xTF32, pre-split, cp.async 2-stage) ----
// Template: BM (block M), WM x WN (warp tile). BN = 128 fixed. 128 threads,
// 4 warps in 2x2. TBK = 16 (two k-octets per stage). 2 CTAs/SM.
// B-side supports 3-way split (fused QKV): seg = col0/n_each selects
// B/bias/C pointers. For a single matrix pass the same pointers 3x and
// n_each = N.
#define TBK16 16
#define A_ST 20
#define B_ST 136

template<int BM, int WM, int WN>
__global__ __launch_bounds__(128, 2) void gemm_tc(
    const float* __restrict__ Ahg, const float* __restrict__ Alg,
    const float* __restrict__ Bh0, const float* __restrict__ Bl0,
    const float* __restrict__ Bh1, const float* __restrict__ Bl1,
    const float* __restrict__ Bh2, const float* __restrict__ Bl2,
    const float* __restrict__ bias0, const float* __restrict__ bias1,
    const float* __restrict__ bias2sel,
    const float* __restrict__ biasadd,
    const float* __restrict__ rowvec, const float* __restrict__ colvec,
    const float* __restrict__ residual,
    float* __restrict__ C0, float* __restrict__ C1, float* __restrict__ C2,
    float* __restrict__ Chi, float* __restrict__ Clo,
    int M, int n_each, int K, int gelu_flag)
{
    constexpr int MT = WM / 16;
    constexpr int NT = WN / 8;
    constexpr int OFF_AL = BM * A_ST;
    constexpr int OFF_BH = 2 * BM * A_ST;
    constexpr int OFF_BL = 2 * BM * A_ST + TBK16 * B_ST;
    constexpr int STAGE  = 2 * BM * A_ST + 2 * TBK16 * B_ST;
    constexpr int A_ITERS = BM / 32;   // float4 loads per thread per half

    extern __shared__ float smbuf[];
    const uint32_t sm_u32 = (uint32_t)__cvta_generic_to_shared(smbuf);
    const float* cur = smbuf;
    uint32_t cur_u32 = sm_u32;
    uint32_t nxt_u32 = sm_u32 + STAGE * 4;

    const int tid  = threadIdx.x;
    const int warp = tid >> 5;
    const int lane = tid & 31;
    const int g    = lane >> 2;
    const int tig  = lane & 3;
    const int wm   = (warp >> 1) * WM;
    const int wn   = (warp & 1) * WN;

    const int row0  = blockIdx.y * BM;
    const int col0g = blockIdx.x * 128;
    const int seg   = col0g / n_each;
    const int col0  = col0g - seg * n_each;

    const float* Bhg = (seg == 0) ? Bh0 : (seg == 1) ? Bh1 : Bh2;
    const float* Blg = (seg == 0) ? Bl0 : (seg == 1) ? Bl1 : Bl2;
    const float* bias = (seg == 0) ? bias0 : (seg == 1) ? bias1 : bias2sel;
    float* Cg = (seg == 0) ? C0 : (seg == 1) ? C1 : C2;

    float acc[MT][NT][4];
    #pragma unroll
    for (int mt = 0; mt < MT; mt++)
        #pragma unroll
        for (int nt = 0; nt < NT; nt++)
            #pragma unroll
            for (int r = 0; r < 4; r++) acc[mt][nt][r] = 0.f;

    // stage loader (cp.async)
    auto issue_stage = [&](uint32_t st_u32, int k0) {
        #pragma unroll
        for (int it = 0; it < A_ITERS; it++) {
            const int s  = tid + it * 128;
            const int ar = s >> 2, ac = (s & 3) * 4;
            const size_t go = (size_t)(row0 + ar) * K + k0 + ac;
            cp16(st_u32 + (ar * A_ST + ac) * 4, Ahg + go);
            cp16(st_u32 + (OFF_AL + ar * A_ST + ac) * 4, Alg + go);
        }
        #pragma unroll
        for (int it = 0; it < 4; it++) {
            const int s  = tid + it * 128;
            const int br = s >> 5, bc = (s & 31) * 4;
            const size_t go = (size_t)(k0 + br) * n_each + col0 + bc;
            cp16(st_u32 + (OFF_BH + br * B_ST + bc) * 4, Bhg + go);
            cp16(st_u32 + (OFF_BL + br * B_ST + bc) * 4, Blg + go);
        }
    };

    issue_stage(cur_u32, 0);
    CP_COMMIT();
    CP_WAIT0();
    __syncthreads();

    const int nk = K / TBK16;
    for (int ki = 0; ki < nk; ki++) {
        const bool more = (ki + 1 < nk);
        if (more) {
            issue_stage(nxt_u32, (ki + 1) * TBK16);
            CP_COMMIT();
        }

        const float* Ah = cur;
        const float* Al = cur + OFF_AL;
        const float* Bh = cur + OFF_BH;
        const float* Bl = cur + OFF_BL;
        #pragma unroll
        for (int kk = 0; kk < TBK16; kk += 8) {
            unsigned ah[MT][4], al[MT][4];
            #pragma unroll
            for (int mt = 0; mt < MT; mt++) {
                const int m = wm + mt * 16;
                const int r0i = (m + g) * A_ST + kk + tig;
                const int r1i = (m + g + 8) * A_ST + kk + tig;
                ah[mt][0] = __float_as_uint(Ah[r0i]);
                ah[mt][1] = __float_as_uint(Ah[r1i]);
                ah[mt][2] = __float_as_uint(Ah[r0i + 4]);
                ah[mt][3] = __float_as_uint(Ah[r1i + 4]);
                al[mt][0] = __float_as_uint(Al[r0i]);
                al[mt][1] = __float_as_uint(Al[r1i]);
                al[mt][2] = __float_as_uint(Al[r0i + 4]);
                al[mt][3] = __float_as_uint(Al[r1i + 4]);
            }
            unsigned bh[NT][2], bl[NT][2];
            #pragma unroll
            for (int nt = 0; nt < NT; nt++) {
                const int n = wn + nt * 8 + g;
                const int c0i = (kk + tig) * B_ST + n;
                const int c1i = (kk + tig + 4) * B_ST + n;
                bh[nt][0] = __float_as_uint(Bh[c0i]);
                bh[nt][1] = __float_as_uint(Bh[c1i]);
                bl[nt][0] = __float_as_uint(Bl[c0i]);
                bl[nt][1] = __float_as_uint(Bl[c1i]);
            }
            #pragma unroll
            for (int mt = 0; mt < MT; mt++)
                #pragma unroll
                for (int nt = 0; nt < NT; nt++) {
                    mma_tf32(acc[mt][nt], ah[mt][0], ah[mt][1], ah[mt][2], ah[mt][3],
                             bh[nt][0], bh[nt][1]);
                    mma_tf32(acc[mt][nt], al[mt][0], al[mt][1], al[mt][2], al[mt][3],
                             bh[nt][0], bh[nt][1]);
                    mma_tf32(acc[mt][nt], ah[mt][0], ah[mt][1], ah[mt][2], ah[mt][3],
                             bl[nt][0], bl[nt][1]);
                }
        }

        if (more) CP_WAIT0();
        __syncthreads();
        { uint32_t t = cur_u32; cur_u32 = nxt_u32; nxt_u32 = t; }
        cur = smbuf + (cur_u32 - sm_u32) / 4;
    }

    // ---- epilogue
    #pragma unroll
    for (int mt = 0; mt < MT; mt++) {
        #pragma unroll
        for (int half = 0; half < 2; half++) {
            const int r = row0 + wm + mt * 16 + g + half * 8;
            const float rv = rowvec ? rowvec[r] : 0.f;
            #pragma unroll
            for (int nt = 0; nt < NT; nt++) {
                const int c = col0 + wn + nt * 8 + 2 * tig;
                float v0 = acc[mt][nt][half * 2 + 0];
                float v1 = acc[mt][nt][half * 2 + 1];
                if (bias)   { v0 += bias[c];  v1 += bias[c + 1]; }
                if (biasadd){ v0 += biasadd[c]; v1 += biasadd[c + 1]; }
                if (rowvec) { v0 += rv * colvec[c]; v1 += rv * colvec[c + 1]; }
                if (gelu_flag) {
                    v0 = 0.5f * v0 * (1.f + erff(v0 * 0.70710678118654752f));
                    v1 = 0.5f * v1 * (1.f + erff(v1 * 0.70710678118654752f));
                }
                if (residual) {
                    float2 rr = *(const float2*)(residual + (size_t)r * n_each + c);
                    v0 += rr.x; v1 += rr.y;
                }
                if (Chi) {
                    float h0, l0, h1, l1;
                    split_tf32(v0, h0, l0); split_tf32(v1, h1, l1);
                    float2 o;
                    o.x = h0; o.y = h1; *(float2*)(Chi + (size_t)r * n_each + c) = o;
                    o.x = l0; o.y = l1; *(float2*)(Clo + (size_t)r * n_each + c) = o;
                } else {
                    float2 o; o.x = v0; o.y = v1;
                    *(float2*)(Cg + (size_t)r * n_each + c) = o;
                }
            }
        }
    }
}

// instantiations
#define BIG_SMEM  ((2*128*A_ST + 2*TBK16*B_ST) * 2 * 4)   // 75,776 B
#define SLIM_SMEM ((2*64*A_ST  + 2*TBK16*B_ST) * 2 * 4)   // 55,296 B

// ---------------- LayerNorm: one block per token, split output -------------
__global__ __launch_bounds__(256) void ln_kernel(
    const float* __restrict__ x, const float* __restrict__ g,
    const float* __restrict__ bta,
    float* __restrict__ out_hi, float* __restrict__ out_lo)
{
    const int t = blockIdx.x;
    const int tid = threadIdx.x;
    const float* xr = x + (size_t)t * D_;

    float v[4];
    float s = 0.f, s2 = 0.f;
    #pragma unroll
    for (int i = 0; i < 4; i++) {
        v[i] = xr[tid + i*256];
        s  += v[i];
        s2 += v[i] * v[i];
    }
    #pragma unroll
    for (int o = 16; o; o >>= 1) {
        s  += __shfl_xor_sync(0xffffffffu, s,  o);
        s2 += __shfl_xor_sync(0xffffffffu, s2, o);
    }
    __shared__ float ss[8], ss2[8];
    if ((tid & 31) == 0) { ss[tid >> 5] = s; ss2[tid >> 5] = s2; }
    __syncthreads();
    s = 0.f; s2 = 0.f;
    #pragma unroll
    for (int w = 0; w < 8; w++) { s += ss[w]; s2 += ss2[w]; }

    const float mean = s * (1.f / D_);
    const float var  = s2 * (1.f / D_) - mean * mean;
    const float inv  = rsqrtf(var + 1e-5f);

    #pragma unroll
    for (int i = 0; i < 4; i++) {
        const int c = tid + i*256;
        const float val = (v[i] - mean) * inv * g[c] + bta[c];
        float hi, lo;
        split_tf32(val, hi, lo);
        out_hi[(size_t)t * D_ + c] = hi;
        out_lo[(size_t)t * D_ + c] = lo;
    }
}

// ---------------- RoPE (in-place, one thread owns the rotation pair) -------
__global__ __launch_bounds__(256) void rope_kernel(float* __restrict__ x)
{
    const int idx = blockIdx.x * 256 + threadIdx.x;
    const int j = idx & 31;
    const int h = (idx >> 5) & 15;
    const int t = idx >> 9;
    const int s = t >> 2;

    const float inv_freq = powf(10000.f, -((float)(2*j)) * (1.f / HD_));
    float sn, c;
    sincosf((float)s * inv_freq, &sn, &c);

    float* base = x + (size_t)t * D_ + h * HD_;
    const float x1 = base[j];
    const float x2 = base[j + 32];
    base[j]      = x1 * c - x2 * sn;
    base[j + 32] = x2 * c + x1 * sn;
}

// ---------------- scores = scale * Q K^T, masked ---------------------------
__global__ __launch_bounds__(256) void qk_kernel(
    const float* __restrict__ q, const float* __restrict__ k,
    const int* __restrict__ mask, float* __restrict__ scores)
{
    const int bh = blockIdx.z;
    const int b = bh >> 4;
    const int h = bh & 15;
    const int qt = blockIdx.y * 64;
    const int kt = blockIdx.x * 64;

    __shared__ float Qs[HD_][65];
    __shared__ float Ks[HD_][65];

    const int tid = threadIdx.x;
    const int ty = tid >> 4, tx = tid & 15;
    const int lr = tid >> 4;
    const int lc = (tid & 15) * 4;

    #pragma unroll
    for (int it = 0; it < 4; it++) {
        const int m = lr + it*16;
        float4 a = *(const float4*)(q + ((size_t)(qt + m) * B_ + b) * D_ + h*HD_ + lc);
        Qs[lc+0][m]=a.x; Qs[lc+1][m]=a.y; Qs[lc+2][m]=a.z; Qs[lc+3][m]=a.w;
        float4 bb = *(const float4*)(k + ((size_t)(kt + m) * B_ + b) * D_ + h*HD_ + lc);
        Ks[lc+0][m]=bb.x; Ks[lc+1][m]=bb.y; Ks[lc+2][m]=bb.z; Ks[lc+3][m]=bb.w;
    }
    __syncthreads();

    float acc[4][4];
    #pragma unroll
    for (int i = 0; i < 4; i++)
        #pragma unroll
        for (int j = 0; j < 4; j++) acc[i][j] = 0.f;

    #pragma unroll
    for (int kk = 0; kk < HD_; kk++) {
        float av[4], bv[4];
        #pragma unroll
        for (int i = 0; i < 4; i++) av[i] = Qs[kk][ty*4 + i];
        #pragma unroll
        for (int j = 0; j < 4; j++) bv[j] = Ks[kk][tx*4 + j];
        #pragma unroll
        for (int i = 0; i < 4; i++)
            #pragma unroll
            for (int j = 0; j < 4; j++)
                acc[i][j] = fmaf(av[i], bv[j], acc[i][j]);
    }

    const float scale = 0.125f;
    #pragma unroll
    for (int i = 0; i < 4; i++) {
        const int qpos = qt + ty*4 + i;
        float* out = scores + ((size_t)bh * S_ + qpos) * S_;
        #pragma unroll
        for (int j = 0; j < 4; j++) {
            const int kpos = kt + tx*4 + j;
            float vsc = acc[i][j] * scale;
            if (mask[b * S_ + kpos] != 0) vsc = -1e30f;
            out[kpos] = vsc;
        }
    }
}

// ---------------- row softmax over 512 keys --------------------------------
__global__ __launch_bounds__(128) void softmax_kernel(float* __restrict__ scores)
{
    const size_t row = blockIdx.x;
    float* p = scores + row * S_;
    const int tid = threadIdx.x;

    float vals[4];
    float m = -3.0e38f;
    #pragma unroll
    for (int i = 0; i < 4; i++) { vals[i] = p[tid + i*128]; m = fmaxf(m, vals[i]); }
    #pragma unroll
    for (int o = 16; o; o >>= 1) m = fmaxf(m, __shfl_xor_sync(0xffffffffu, m, o));
    __shared__ float sm[4], ssum[4];
    if ((tid & 31) == 0) sm[tid >> 5] = m;
    __syncthreads();
    m = fmaxf(fmaxf(sm[0], sm[1]), fmaxf(sm[2], sm[3]));

    float s = 0.f;
    #pragma unroll
    for (int i = 0; i < 4; i++) { vals[i] = __expf(vals[i] - m); s += vals[i]; }
    #pragma unroll
    for (int o = 16; o; o >>= 1) s += __shfl_xor_sync(0xffffffffu, s, o);
    if ((tid & 31) == 0) ssum[tid >> 5] = s;
    __syncthreads();
    const float inv = 1.f / (ssum[0] + ssum[1] + ssum[2] + ssum[3]);

    #pragma unroll
    for (int i = 0; i < 4; i++) p[tid + i*128] = vals[i] * inv;
}

// ---------------- attn = probs @ V, split-scattered to [t, d] layout -------
__global__ __launch_bounds__(256) void pv_kernel(
    const float* __restrict__ scores, const float* __restrict__ v,
    float* __restrict__ attn_hi, float* __restrict__ attn_lo)
{
    const int bh = blockIdx.z;
    const int b = bh >> 4, h = bh & 15;
    const int qt = blockIdx.y * 64;

    __shared__ float Ps[32][65];
    __shared__ float Vs[32][64];

    const int tid = threadIdx.x;
    const int ty = tid >> 4, tx = tid & 15;
    const int pr = tid >> 3;
    const int pc = (tid & 7) * 4;
    const int vr = tid >> 4;
    const int vc = (tid & 15) * 4;

    float acc[4][4];
    #pragma unroll
    for (int i = 0; i < 4; i++)
        #pragma unroll
        for (int j = 0; j < 4; j++) acc[i][j] = 0.f;

    for (int kt = 0; kt < S_; kt += 32) {
        #pragma unroll
        for (int it = 0; it < 2; it++) {
            const int m = pr + it*32;
            float4 a = *(const float4*)(scores + ((size_t)bh*S_ + qt + m)*S_ + kt + pc);
            Ps[pc+0][m]=a.x; Ps[pc+1][m]=a.y; Ps[pc+2][m]=a.z; Ps[pc+3][m]=a.w;
        }
        #pragma unroll
        for (int it = 0; it < 2; it++) {
            const int kr = vr + it*16;
            float4 bb = *(const float4*)(v + ((size_t)(kt + kr)*B_ + b)*D_ + h*HD_ + vc);
            *(float4*)&Vs[kr][vc] = bb;
        }
        __syncthreads();

        #pragma unroll
        for (int kk = 0; kk < 32; kk++) {
            float av[4], bv[4];
            #pragma unroll
            for (int i = 0; i < 4; i++) av[i] = Ps[kk][ty*4 + i];
            #pragma unroll
            for (int j = 0; j < 4; j++) bv[j] = Vs[kk][tx*4 + j];
            #pragma unroll
            for (int i = 0; i < 4; i++)
                #pragma unroll
                for (int j = 0; j < 4; j++)
                    acc[i][j] = fmaf(av[i], bv[j], acc[i][j]);
        }
        __syncthreads();
    }

    #pragma unroll
    for (int i = 0; i < 4; i++) {
        const int qpos = qt + ty*4 + i;
        const size_t base = ((size_t)qpos * B_ + b) * D_ + h*HD_;
        #pragma unroll
        for (int j = 0; j < 4; j++) {
            float hi, lo;
            split_tf32(acc[i][j], hi, lo);
            attn_hi[base + tx*4 + j] = hi;
            attn_lo[base + tx*4 + j] = lo;
        }
    }
}

// ---------------- host orchestration ---------------------------------------
static inline void launch_split(const float* in, float* hi, float* lo, size_t n)
{
    split_arr<<<1184, 256>>>((const float4*)in, (float4*)hi, (float4*)lo, (int)(n / 4));
}

extern "C" void kernel_launch(void* const* d_in, const int* in_sizes, int n_in,
                              void* d_out, int out_size)
{
    (void)in_sizes; (void)n_in; (void)out_size;

    const float* segments  = (const float*)d_in[0];
    const float* durations = (const float*)d_in[1];
    const int*   padmask   = (const int*)d_in[2];
    const float* Wproj = (const float*)d_in[3];
    const float* bproj = (const float*)d_in[4];
    const float* Wdur  = (const float*)d_in[5];
    const float* bdur  = (const float*)d_in[6];
    const float* ln1_g = (const float*)d_in[7];
    const float* ln1_b = (const float*)d_in[8];
    const float* Wq = (const float*)d_in[9];
    const float* bq = (const float*)d_in[10];
    const float* Wk = (const float*)d_in[11];
    const float* bk = (const float*)d_in[12];
    const float* Wv = (const float*)d_in[13];
    const float* bv = (const float*)d_in[14];
    const float* Wo = (const float*)d_in[15];
    const float* bo = (const float*)d_in[16];
    const float* ln2_g = (const float*)d_in[17];
    const float* ln2_b = (const float*)d_in[18];
    const float* Wff1 = (const float*)d_in[19];
    const float* bff1 = (const float*)d_in[20];
    const float* Wff2 = (const float*)d_in[21];
    const float* bff2 = (const float*)d_in[22];

    float* x = (float*)d_out;

    float *q, *k, *v, *scores;
    float *h_hi, *h_lo, *attn_hi, *attn_lo, *ff_hi, *ff_lo;
    float *seg_hi, *seg_lo, *wproj_hi, *wproj_lo;
    float *wq_hi, *wq_lo, *wk_hi, *wk_lo, *wv_hi, *wv_lo, *wo_hi, *wo_lo;
    float *w1_hi, *w1_lo, *w2_hi, *w2_lo;
    cudaGetSymbolAddress((void**)&q,       g_q);
    cudaGetSymbolAddress((void**)&k,       g_k);
    cudaGetSymbolAddress((void**)&v,       g_v);
    cudaGetSymbolAddress((void**)&scores,  g_scores);
    cudaGetSymbolAddress((void**)&h_hi,    g_h_hi);
    cudaGetSymbolAddress((void**)&h_lo,    g_h_lo);
    cudaGetSymbolAddress((void**)&attn_hi, g_attn_hi);
    cudaGetSymbolAddress((void**)&attn_lo, g_attn_lo);
    cudaGetSymbolAddress((void**)&ff_hi,   g_ff_hi);
    cudaGetSymbolAddress((void**)&ff_lo,   g_ff_lo);
    cudaGetSymbolAddress((void**)&seg_hi,  g_seg_hi);
    cudaGetSymbolAddress((void**)&seg_lo,  g_seg_lo);
    cudaGetSymbolAddress((void**)&wproj_hi,g_wproj_hi);
    cudaGetSymbolAddress((void**)&wproj_lo,g_wproj_lo);
    cudaGetSymbolAddress((void**)&wq_hi,   g_wq_hi);
    cudaGetSymbolAddress((void**)&wq_lo,   g_wq_lo);
    cudaGetSymbolAddress((void**)&wk_hi,   g_wk_hi);
    cudaGetSymbolAddress((void**)&wk_lo,   g_wk_lo);
    cudaGetSymbolAddress((void**)&wv_hi,   g_wv_hi);
    cudaGetSymbolAddress((void**)&wv_lo,   g_wv_lo);
    cudaGetSymbolAddress((void**)&wo_hi,   g_wo_hi);
    cudaGetSymbolAddress((void**)&wo_lo,   g_wo_lo);
    cudaGetSymbolAddress((void**)&w1_hi,   g_w1_hi);
    cudaGetSymbolAddress((void**)&w1_lo,   g_w1_lo);
    cudaGetSymbolAddress((void**)&w2_hi,   g_w2_hi);
    cudaGetSymbolAddress((void**)&w2_lo,   g_w2_lo);

    cudaFuncSetAttribute(gemm_tc<128,64,64>,
        cudaFuncAttributeMaxDynamicSharedMemorySize, BIG_SMEM);
    cudaFuncSetAttribute(gemm_tc<64,32,64>,
        cudaFuncAttributeMaxDynamicSharedMemorySize, SLIM_SMEM);

    // ---- prep pass
    launch_split(segments, seg_hi, seg_lo, (size_t)T_*DIN_);
    launch_split(Wproj, wproj_hi, wproj_lo, (size_t)DIN_*D_);
    launch_split(Wq, wq_hi, wq_lo, (size_t)L_*D_*D_);
    launch_split(Wk, wk_hi, wk_lo, (size_t)L_*D_*D_);
    launch_split(Wv, wv_hi, wv_lo, (size_t)L_*D_*D_);
    launch_split(Wo, wo_hi, wo_lo, (size_t)L_*D_*D_);
    launch_split(Wff1, w1_hi, w1_lo, (size_t)L_*D_*F_);
    launch_split(Wff2, w2_hi, w2_lo, (size_t)L_*F_*D_);

    const dim3 blk(128);

    // proj: x = segments @ Wproj + bproj + durations*Wdur + bdur
    gemm_tc<64,32,64><<<dim3(D_/128, T_/64), blk, SLIM_SMEM>>>(
        seg_hi, seg_lo,
        wproj_hi, wproj_lo, wproj_hi, wproj_lo, wproj_hi, wproj_lo,
        bproj, bproj, bproj, bdur, durations, Wdur, nullptr,
        x, x, x, nullptr, nullptr, T_, D_, DIN_, 0);

    for (int l = 0; l < L_; l++) {
        const size_t od = (size_t)l*D_*D_;
        const size_t o1 = (size_t)l*D_*F_;
        const size_t o2 = (size_t)l*F_*D_;

        ln_kernel<<<T_, 256>>>(x, ln1_g + l*D_, ln1_b + l*D_, h_hi, h_lo);

        // fused QKV: N_total = 3072, per-CTA select
        gemm_tc<128,64,64><<<dim3(3*D_/128, T_/128), blk, BIG_SMEM>>>(
            h_hi, h_lo,
            wq_hi + od, wq_lo + od, wk_hi + od, wk_lo + od, wv_hi + od, wv_lo + od,
            bq + l*D_, bk + l*D_, bv + l*D_,
            nullptr, nullptr, nullptr, nullptr,
            q, k, v, nullptr, nullptr, T_, D_, D_, 0);

        rope_kernel<<<(T_*H_*32)/256, 256>>>(q);
        rope_kernel<<<(T_*H_*32)/256, 256>>>(k);

        qk_kernel<<<dim3(S_/64, S_/64, B_*H_), dim3(256)>>>(q, k, padmask, scores);
        softmax_kernel<<<B_*H_*S_, 128>>>(scores);
        pv_kernel<<<dim3(1, S_/64, B_*H_), dim3(256)>>>(scores, v, attn_hi, attn_lo);

        // x = x + attn @ Wo + bo
        gemm_tc<64,32,64><<<dim3(D_/128, T_/64), blk, SLIM_SMEM>>>(
            attn_hi, attn_lo,
            wo_hi + od, wo_lo + od, wo_hi + od, wo_lo + od, wo_hi + od, wo_lo + od,
            bo + l*D_, bo + l*D_, bo + l*D_,
            nullptr, nullptr, nullptr, x,
            x, x, x, nullptr, nullptr, T_, D_, D_, 0);

        ln_kernel<<<T_, 256>>>(x, ln2_g + l*D_, ln2_b + l*D_, h_hi, h_lo);

        // ff = gelu(h @ W1 + b1), split output
        gemm_tc<128,64,64><<<dim3(F_/128, T_/128), blk, BIG_SMEM>>>(
            h_hi, h_lo,
            w1_hi + o1, w1_lo + o1, w1_hi + o1, w1_lo + o1, w1_hi + o1, w1_lo + o1,
            bff1 + l*F_, bff1 + l*F_, bff1 + l*F_,
            nullptr, nullptr, nullptr, nullptr,
            nullptr, nullptr, nullptr, ff_hi, ff_lo, T_, F_, D_, 1);

        // x = x + ff @ W2 + b2
        gemm_tc<64,32,64><<<dim3(D_/128, T_/64), blk, SLIM_SMEM>>>(
            ff_hi, ff_lo,
            w2_hi + o2, w2_lo + o2, w2_hi + o2, w2_lo + o2, w2_hi + o2, w2_lo + o2,
            bff2 + l*D_, bff2 + l*D_, bff2 + l*D_,
            nullptr, nullptr, nullptr, x,
            x, x, x, nullptr, nullptr, T_, D_, F_, 0);
    }
}

// round 9
// speedup vs baseline: 1.6956x; 1.6956x over previous
#include <cuda_runtime.h>
#include <math.h>
#include <stdint.h>

#define L_   12
#define S_   512
#define B_   4
#define DIN_ 768
#define D_   1024
#define H_   16
#define F_   4096
#define HD_  64
#define T_   (S_*B_)   // 2048 tokens

// ---------------- scratch (static device globals; no runtime allocation) ----
__device__ float g_h[T_*D_];
__device__ float g_q[T_*D_];
__device__ float g_k[T_*D_];
__device__ float g_v[T_*D_];
__device__ float g_attn[T_*D_];
__device__ float g_ff[(size_t)T_*F_];
__device__ float g_scores[(size_t)B_*H_*S_*S_];   // 67 MB

// ---------------- bf16 split helpers ---------------------------------------
// pack two floats as bf16x2: {lower = x0, upper = x1}
__device__ __forceinline__ unsigned pack_bf16(float x0, float x1) {
    unsigned u;
    asm("cvt.rn.bf16x2.f32 %0, %1, %2;" : "=r"(u) : "f"(x1), "f"(x0));
    return u;
}
// split a float4 (4 consecutive k) into hi/lo bf16x2 pairs
__device__ __forceinline__ void split4_bf16(float4 v, unsigned& h0, unsigned& h1,
                                            unsigned& l0, unsigned& l1)
{
    h0 = pack_bf16(v.x, v.y);
    h1 = pack_bf16(v.z, v.w);
    const float hx = __uint_as_float(h0 << 16);
    const float hy = __uint_as_float(h0 & 0xffff0000u);
    const float hz = __uint_as_float(h1 << 16);
    const float hw = __uint_as_float(h1 & 0xffff0000u);
    l0 = pack_bf16(v.x - hx, v.y - hy);
    l1 = pack_bf16(v.z - hz, v.w - hw);
}
// pack across two rows (for B): {lower = r0val (k even), upper = r1val (k odd)}
__device__ __forceinline__ void splitp_bf16(float a, float b, unsigned& h, unsigned& l)
{
    h = pack_bf16(a, b);
    const float ha = __uint_as_float(h << 16);
    const float hb = __uint_as_float(h & 0xffff0000u);
    l = pack_bf16(a - ha, b - hb);
}

__device__ __forceinline__ void mma_bf16(float c[4],
    unsigned a0, unsigned a1, unsigned a2, unsigned a3,
    unsigned b0, unsigned b1)
{
    asm volatile(
        "mma.sync.aligned.m16n8k16.row.col.f32.bf16.bf16.f32 "
        "{%0,%1,%2,%3}, {%4,%5,%6,%7}, {%8,%9}, {%0,%1,%2,%3};"
        : "+f"(c[0]), "+f"(c[1]), "+f"(c[2]), "+f"(c[3])
        : "r"(a0), "r"(a1), "r"(a2), "r"(a3), "r"(b0), "r"(b1));
}

// ---------------- tensor-core GEMM (3x bf16 split, double-buffered) --------
// C = A[MxK] @ W[KxN] + bias[c] + bias2[c] + rowvec[r]*colvec[c];
// optional exact GELU; + residual[r,c]
// block tile 128x128x32, 8 warps (2x4), warp tile 64x32, m16n8k16 bf16
// smem per stage (u32 units): Ah/Al [128][20], Bh/Bl [16][136]
#define TBM 128
#define TBN 128
#define TBK 32
#define A_STU 20
#define B_STU 136
#define OFF_ALU (TBM*A_STU)                    // 2560
#define OFF_BHU (2*TBM*A_STU)                  // 5120
#define OFF_BLU (2*TBM*A_STU + (TBK/2)*B_STU)  // 7296
#define STAGE_U (2*TBM*A_STU + 2*(TBK/2)*B_STU)   // 9472
#define SMEM_BYTES (2*STAGE_U*4)               // 75776

__device__ __forceinline__ void store_split_tile(
    unsigned* stage, int tid, const float4* pa,
    const float4* pb0, const float4* pb1)
{
    // A: 128x32 floats -> hi/lo bf16x2 [128][16] u32
    #pragma unroll
    for (int it = 0; it < 4; it++) {
        const int s = tid + it * 256;
        const int r = s >> 3, kc = (s & 7) * 4;     // k offset in floats
        unsigned h0, h1, l0, l1;
        split4_bf16(pa[it], h0, h1, l0, l1);
        uint2 hv; hv.x = h0; hv.y = h1;
        uint2 lv; lv.x = l0; lv.y = l1;
        *(uint2*)&stage[r * A_STU + (kc >> 1)]           = hv;
        *(uint2*)&stage[OFF_ALU + r * A_STU + (kc >> 1)] = lv;
    }
    // B: 32x128 floats -> k-pair packed hi/lo [16][128] u32
    #pragma unroll
    for (int it = 0; it < 2; it++) {
        const int s = tid + it * 256;
        const int p  = s >> 5;            // k-pair 0..15
        const int nq = (s & 31) * 4;      // n offset
        uint4 hv, lv;
        splitp_bf16(pb0[it].x, pb1[it].x, hv.x, lv.x);
        splitp_bf16(pb0[it].y, pb1[it].y, hv.y, lv.y);
        splitp_bf16(pb0[it].z, pb1[it].z, hv.z, lv.z);
        splitp_bf16(pb0[it].w, pb1[it].w, hv.w, lv.w);
        *(uint4*)&stage[OFF_BHU + p * B_STU + nq] = hv;
        *(uint4*)&stage[OFF_BLU + p * B_STU + nq] = lv;
    }
}

__global__ __launch_bounds__(256, 1) void gemm_tc(
    const float* __restrict__ A, const float* __restrict__ Bw,
    const float* __restrict__ bias, const float* __restrict__ bias2,
    const float* __restrict__ rowvec, const float* __restrict__ colvec,
    const float* __restrict__ residual,
    float* __restrict__ C, int M, int N, int K, int gelu_flag)
{
    extern __shared__ unsigned smbuf[];
    unsigned* cur = smbuf;
    unsigned* nxt = smbuf + STAGE_U;

    const int tid  = threadIdx.x;
    const int warp = tid >> 5;
    const int lane = tid & 31;
    const int g    = lane >> 2;      // 0..7
    const int tig  = lane & 3;       // 0..3
    const int wm   = (warp >> 2) * 64;   // 0 or 64
    const int wn   = (warp & 3) * 32;    // 0,32,64,96

    const int row0 = blockIdx.y * TBM;
    const int col0 = blockIdx.x * TBN;

    float acc[4][4][4];
    #pragma unroll
    for (int mt = 0; mt < 4; mt++)
        #pragma unroll
        for (int nt = 0; nt < 4; nt++)
            #pragma unroll
            for (int r = 0; r < 4; r++) acc[mt][nt][r] = 0.f;

    float4 pa[4], pb0[2], pb1[2];

    // ---- prologue: load tile 0 and split into cur
    #pragma unroll
    for (int it = 0; it < 4; it++) {
        const int s = tid + it * 256;
        pa[it] = *(const float4*)(A + (size_t)(row0 + (s >> 3)) * K + (s & 7) * 4);
    }
    #pragma unroll
    for (int it = 0; it < 2; it++) {
        const int s = tid + it * 256;
        const int p = s >> 5, nq = (s & 31) * 4;
        pb0[it] = *(const float4*)(Bw + (size_t)(2 * p)     * N + col0 + nq);
        pb1[it] = *(const float4*)(Bw + (size_t)(2 * p + 1) * N + col0 + nq);
    }
    store_split_tile(cur, tid, pa, pb0, pb1);
    __syncthreads();

    const int nk = K / TBK;
    for (int ki = 0; ki < nk; ki++) {
        const bool more = (ki + 1 < nk);
        // ---- prefetch next tile into registers
        if (more) {
            const int k0n = (ki + 1) * TBK;
            #pragma unroll
            for (int it = 0; it < 4; it++) {
                const int s = tid + it * 256;
                pa[it] = *(const float4*)(A + (size_t)(row0 + (s >> 3)) * K + k0n + (s & 7) * 4);
            }
            #pragma unroll
            for (int it = 0; it < 2; it++) {
                const int s = tid + it * 256;
                const int p = s >> 5, nq = (s & 31) * 4;
                pb0[it] = *(const float4*)(Bw + (size_t)(k0n + 2 * p)     * N + col0 + nq);
                pb1[it] = *(const float4*)(Bw + (size_t)(k0n + 2 * p + 1) * N + col0 + nq);
            }
        }

        // ---- compute current stage: 2 x k16 steps, pure LDS + MMA
        const unsigned* Ah = cur;
        const unsigned* Al = cur + OFF_ALU;
        const unsigned* Bh = cur + OFF_BHU;
        const unsigned* Bl = cur + OFF_BLU;
        #pragma unroll
        for (int st = 0; st < 2; st++) {
            const int pb = st * 8;       // k-pair base
            unsigned ah[4][4], al[4][4];
            #pragma unroll
            for (int mt = 0; mt < 4; mt++) {
                const int m = wm + mt * 16;
                const int r0i = (m + g) * A_STU + pb + tig;
                const int r1i = (m + g + 8) * A_STU + pb + tig;
                ah[mt][0] = Ah[r0i];     ah[mt][1] = Ah[r1i];
                ah[mt][2] = Ah[r0i + 4]; ah[mt][3] = Ah[r1i + 4];
                al[mt][0] = Al[r0i];     al[mt][1] = Al[r1i];
                al[mt][2] = Al[r0i + 4]; al[mt][3] = Al[r1i + 4];
            }
            unsigned bh[4][2], bl[4][2];
            #pragma unroll
            for (int nt = 0; nt < 4; nt++) {
                const int n = wn + nt * 8 + g;
                const int c0i = (pb + tig) * B_STU + n;
                const int c1i = (pb + tig + 4) * B_STU + n;
                bh[nt][0] = Bh[c0i]; bh[nt][1] = Bh[c1i];
                bl[nt][0] = Bl[c0i]; bl[nt][1] = Bl[c1i];
            }
            #pragma unroll
            for (int mt = 0; mt < 4; mt++)
                #pragma unroll
                for (int nt = 0; nt < 4; nt++) {
                    mma_bf16(acc[mt][nt], ah[mt][0], ah[mt][1], ah[mt][2], ah[mt][3],
                             bh[nt][0], bh[nt][1]);
                    mma_bf16(acc[mt][nt], al[mt][0], al[mt][1], al[mt][2], al[mt][3],
                             bh[nt][0], bh[nt][1]);
                    mma_bf16(acc[mt][nt], ah[mt][0], ah[mt][1], ah[mt][2], ah[mt][3],
                             bl[nt][0], bl[nt][1]);
                }
        }

        // ---- split-store prefetched tile into the OTHER stage, single sync
        if (more) store_split_tile(nxt, tid, pa, pb0, pb1);
        __syncthreads();
        unsigned* t = cur; cur = nxt; nxt = t;
    }

    // ---- epilogue (same acc layout as m16n8 f32)
    #pragma unroll
    for (int mt = 0; mt < 4; mt++) {
        #pragma unroll
        for (int half = 0; half < 2; half++) {
            const int r = row0 + wm + mt * 16 + g + half * 8;
            const float rv = rowvec ? rowvec[r] : 0.f;
            #pragma unroll
            for (int nt = 0; nt < 4; nt++) {
                const int c = col0 + wn + nt * 8 + 2 * tig;
                float v0 = acc[mt][nt][half * 2 + 0];
                float v1 = acc[mt][nt][half * 2 + 1];
                if (bias)  { v0 += bias[c];  v1 += bias[c + 1]; }
                if (bias2) { v0 += bias2[c]; v1 += bias2[c + 1]; }
                if (rowvec) { v0 += rv * colvec[c]; v1 += rv * colvec[c + 1]; }
                if (gelu_flag) {
                    v0 = 0.5f * v0 * (1.f + erff(v0 * 0.70710678118654752f));
                    v1 = 0.5f * v1 * (1.f + erff(v1 * 0.70710678118654752f));
                }
                if (residual) {
                    float2 rr = *(const float2*)(residual + (size_t)r * N + c);
                    v0 += rr.x; v1 += rr.y;
                }
                float2 o; o.x = v0; o.y = v1;
                *(float2*)(C + (size_t)r * N + c) = o;
            }
        }
    }
}

// ---------------- LayerNorm: one block per token ---------------------------
__global__ __launch_bounds__(256) void ln_kernel(
    const float* __restrict__ x, const float* __restrict__ g,
    const float* __restrict__ bta, float* __restrict__ out)
{
    const int t = blockIdx.x;
    const int tid = threadIdx.x;
    const float* xr = x + (size_t)t * D_;

    float v[4];
    float s = 0.f, s2 = 0.f;
    #pragma unroll
    for (int i = 0; i < 4; i++) {
        v[i] = xr[tid + i*256];
        s  += v[i];
        s2 += v[i] * v[i];
    }
    #pragma unroll
    for (int o = 16; o; o >>= 1) {
        s  += __shfl_xor_sync(0xffffffffu, s,  o);
        s2 += __shfl_xor_sync(0xffffffffu, s2, o);
    }
    __shared__ float ss[8], ss2[8];
    if ((tid & 31) == 0) { ss[tid >> 5] = s; ss2[tid >> 5] = s2; }
    __syncthreads();
    s = 0.f; s2 = 0.f;
    #pragma unroll
    for (int w = 0; w < 8; w++) { s += ss[w]; s2 += ss2[w]; }

    const float mean = s * (1.f / D_);
    const float var  = s2 * (1.f / D_) - mean * mean;
    const float inv  = rsqrtf(var + 1e-5f);

    float* orow = out + (size_t)t * D_;
    #pragma unroll
    for (int i = 0; i < 4; i++) {
        const int c = tid + i*256;
        orow[c] = (v[i] - mean) * inv * g[c] + bta[c];
    }
}

// ---------------- RoPE (in-place, one thread owns the rotation pair) -------
__global__ __launch_bounds__(256) void rope_kernel(float* __restrict__ x)
{
    const int idx = blockIdx.x * 256 + threadIdx.x;
    const int j = idx & 31;
    const int h = (idx >> 5) & 15;
    const int t = idx >> 9;
    const int s = t >> 2;

    const float inv_freq = powf(10000.f, -((float)(2*j)) * (1.f / HD_));
    float sn, c;
    sincosf((float)s * inv_freq, &sn, &c);

    float* base = x + (size_t)t * D_ + h * HD_;
    const float x1 = base[j];
    const float x2 = base[j + 32];
    base[j]      = x1 * c - x2 * sn;
    base[j + 32] = x2 * c + x1 * sn;
}

// ---------------- scores = scale * Q K^T, masked ---------------------------
__global__ __launch_bounds__(256) void qk_kernel(
    const float* __restrict__ q, const float* __restrict__ k,
    const int* __restrict__ mask, float* __restrict__ scores)
{
    const int bh = blockIdx.z;
    const int b = bh >> 4;
    const int h = bh & 15;
    const int qt = blockIdx.y * 64;
    const int kt = blockIdx.x * 64;

    __shared__ float Qs[HD_][65];
    __shared__ float Ks[HD_][65];

    const int tid = threadIdx.x;
    const int ty = tid >> 4, tx = tid & 15;
    const int lr = tid >> 4;
    const int lc = (tid & 15) * 4;

    #pragma unroll
    for (int it = 0; it < 4; it++) {
        const int m = lr + it*16;
        float4 a = *(const float4*)(q + ((size_t)(qt + m) * B_ + b) * D_ + h*HD_ + lc);
        Qs[lc+0][m]=a.x; Qs[lc+1][m]=a.y; Qs[lc+2][m]=a.z; Qs[lc+3][m]=a.w;
        float4 bb = *(const float4*)(k + ((size_t)(kt + m) * B_ + b) * D_ + h*HD_ + lc);
        Ks[lc+0][m]=bb.x; Ks[lc+1][m]=bb.y; Ks[lc+2][m]=bb.z; Ks[lc+3][m]=bb.w;
    }
    __syncthreads();

    float acc[4][4];
    #pragma unroll
    for (int i = 0; i < 4; i++)
        #pragma unroll
        for (int j = 0; j < 4; j++) acc[i][j] = 0.f;

    #pragma unroll
    for (int kk = 0; kk < HD_; kk++) {
        float av[4], bv[4];
        #pragma unroll
        for (int i = 0; i < 4; i++) av[i] = Qs[kk][ty*4 + i];
        #pragma unroll
        for (int j = 0; j < 4; j++) bv[j] = Ks[kk][tx*4 + j];
        #pragma unroll
        for (int i = 0; i < 4; i++)
            #pragma unroll
            for (int j = 0; j < 4; j++)
                acc[i][j] = fmaf(av[i], bv[j], acc[i][j]);
    }

    const float scale = 0.125f;
    #pragma unroll
    for (int i = 0; i < 4; i++) {
        const int qpos = qt + ty*4 + i;
        float* out = scores + ((size_t)bh * S_ + qpos) * S_;
        #pragma unroll
        for (int j = 0; j < 4; j++) {
            const int kpos = kt + tx*4 + j;
            float vsc = acc[i][j] * scale;
            if (mask[b * S_ + kpos] != 0) vsc = -1e30f;
            out[kpos] = vsc;
        }
    }
}

// ---------------- row softmax over 512 keys --------------------------------
__global__ __launch_bounds__(128) void softmax_kernel(float* __restrict__ scores)
{
    const size_t row = blockIdx.x;
    float* p = scores + row * S_;
    const int tid = threadIdx.x;

    float vals[4];
    float m = -3.0e38f;
    #pragma unroll
    for (int i = 0; i < 4; i++) { vals[i] = p[tid + i*128]; m = fmaxf(m, vals[i]); }
    #pragma unroll
    for (int o = 16; o; o >>= 1) m = fmaxf(m, __shfl_xor_sync(0xffffffffu, m, o));
    __shared__ float sm[4], ssum[4];
    if ((tid & 31) == 0) sm[tid >> 5] = m;
    __syncthreads();
    m = fmaxf(fmaxf(sm[0], sm[1]), fmaxf(sm[2], sm[3]));

    float s = 0.f;
    #pragma unroll
    for (int i = 0; i < 4; i++) { vals[i] = __expf(vals[i] - m); s += vals[i]; }
    #pragma unroll
    for (int o = 16; o; o >>= 1) s += __shfl_xor_sync(0xffffffffu, s, o);
    if ((tid & 31) == 0) ssum[tid >> 5] = s;
    __syncthreads();
    const float inv = 1.f / (ssum[0] + ssum[1] + ssum[2] + ssum[3]);

    #pragma unroll
    for (int i = 0; i < 4; i++) p[tid + i*128] = vals[i] * inv;
}

// ---------------- attn = probs @ V, scattered to [t, d] layout -------------
__global__ __launch_bounds__(256) void pv_kernel(
    const float* __restrict__ scores, const float* __restrict__ v,
    float* __restrict__ attn)
{
    const int bh = blockIdx.z;
    const int b = bh >> 4, h = bh & 15;
    const int qt = blockIdx.y * 64;

    __shared__ float Ps[32][65];
    __shared__ float Vs[32][64];

    const int tid = threadIdx.x;
    const int ty = tid >> 4, tx = tid & 15;
    const int pr = tid >> 3;
    const int pc = (tid & 7) * 4;
    const int vr = tid >> 4;
    const int vc = (tid & 15) * 4;

    float acc[4][4];
    #pragma unroll
    for (int i = 0; i < 4; i++)
        #pragma unroll
        for (int j = 0; j < 4; j++) acc[i][j] = 0.f;

    for (int kt = 0; kt < S_; kt += 32) {
        #pragma unroll
        for (int it = 0; it < 2; it++) {
            const int m = pr + it*32;
            float4 a = *(const float4*)(scores + ((size_t)bh*S_ + qt + m)*S_ + kt + pc);
            Ps[pc+0][m]=a.x; Ps[pc+1][m]=a.y; Ps[pc+2][m]=a.z; Ps[pc+3][m]=a.w;
        }
        #pragma unroll
        for (int it = 0; it < 2; it++) {
            const int kr = vr + it*16;
            float4 bb = *(const float4*)(v + ((size_t)(kt + kr)*B_ + b)*D_ + h*HD_ + vc);
            *(float4*)&Vs[kr][vc] = bb;
        }
        __syncthreads();

        #pragma unroll
        for (int kk = 0; kk < 32; kk++) {
            float av[4], bv[4];
            #pragma unroll
            for (int i = 0; i < 4; i++) av[i] = Ps[kk][ty*4 + i];
            #pragma unroll
            for (int j = 0; j < 4; j++) bv[j] = Vs[kk][tx*4 + j];
            #pragma unroll
            for (int i = 0; i < 4; i++)
                #pragma unroll
                for (int j = 0; j < 4; j++)
                    acc[i][j] = fmaf(av[i], bv[j], acc[i][j]);
        }
        __syncthreads();
    }

    #pragma unroll
    for (int i = 0; i < 4; i++) {
        const int qpos = qt + ty*4 + i;
        float* orow = attn + ((size_t)qpos * B_ + b) * D_ + h*HD_;
        #pragma unroll
        for (int j = 0; j < 4; j++)
            orow[tx*4 + j] = acc[i][j];
    }
}

// ---------------- host orchestration ---------------------------------------
extern "C" void kernel_launch(void* const* d_in, const int* in_sizes, int n_in,
                              void* d_out, int out_size)
{
    (void)in_sizes; (void)n_in; (void)out_size;

    const float* segments  = (const float*)d_in[0];
    const float* durations = (const float*)d_in[1];
    const int*   padmask   = (const int*)d_in[2];   // bool promoted to int32
    const float* Wproj = (const float*)d_in[3];
    const float* bproj = (const float*)d_in[4];
    const float* Wdur  = (const float*)d_in[5];
    const float* bdur  = (const float*)d_in[6];
    const float* ln1_g = (const float*)d_in[7];
    const float* ln1_b = (const float*)d_in[8];
    const float* Wq = (const float*)d_in[9];
    const float* bq = (const float*)d_in[10];
    const float* Wk = (const float*)d_in[11];
    const float* bk = (const float*)d_in[12];
    const float* Wv = (const float*)d_in[13];
    const float* bv = (const float*)d_in[14];
    const float* Wo = (const float*)d_in[15];
    const float* bo = (const float*)d_in[16];
    const float* ln2_g = (const float*)d_in[17];
    const float* ln2_b = (const float*)d_in[18];
    const float* Wff1 = (const float*)d_in[19];
    const float* bff1 = (const float*)d_in[20];
    const float* Wff2 = (const float*)d_in[21];
    const float* bff2 = (const float*)d_in[22];

    float* x = (float*)d_out;

    float *h, *q, *k, *v, *attn, *ff, *scores;
    cudaGetSymbolAddress((void**)&h,      g_h);
    cudaGetSymbolAddress((void**)&q,      g_q);
    cudaGetSymbolAddress((void**)&k,      g_k);
    cudaGetSymbolAddress((void**)&v,      g_v);
    cudaGetSymbolAddress((void**)&attn,   g_attn);
    cudaGetSymbolAddress((void**)&ff,     g_ff);
    cudaGetSymbolAddress((void**)&scores, g_scores);

    cudaFuncSetAttribute(gemm_tc,
        cudaFuncAttributeMaxDynamicSharedMemorySize, SMEM_BYTES);

    const dim3 blk(256);

    // x = segments @ Wproj + bproj + durations*Wdur + bdur
    gemm_tc<<<dim3(D_/TBN, T_/TBM), blk, SMEM_BYTES>>>(
        segments, Wproj, bproj, bdur, durations, Wdur, nullptr,
        x, T_, D_, DIN_, 0);

    for (int l = 0; l < L_; l++) {
        const float* wq = Wq + (size_t)l*D_*D_;
        const float* wk = Wk + (size_t)l*D_*D_;
        const float* wv = Wv + (size_t)l*D_*D_;
        const float* wo = Wo + (size_t)l*D_*D_;
        const float* w1 = Wff1 + (size_t)l*D_*F_;
        const float* w2 = Wff2 + (size_t)l*F_*D_;

        ln_kernel<<<T_, 256>>>(x, ln1_g + l*D_, ln1_b + l*D_, h);

        gemm_tc<<<dim3(D_/TBN, T_/TBM), blk, SMEM_BYTES>>>(h, wq, bq + l*D_,
            nullptr, nullptr, nullptr, nullptr, q, T_, D_, D_, 0);
        gemm_tc<<<dim3(D_/TBN, T_/TBM), blk, SMEM_BYTES>>>(h, wk, bk + l*D_,
            nullptr, nullptr, nullptr, nullptr, k, T_, D_, D_, 0);
        gemm_tc<<<dim3(D_/TBN, T_/TBM), blk, SMEM_BYTES>>>(h, wv, bv + l*D_,
            nullptr, nullptr, nullptr, nullptr, v, T_, D_, D_, 0);

        rope_kernel<<<(T_*H_*32)/256, 256>>>(q);
        rope_kernel<<<(T_*H_*32)/256, 256>>>(k);

        qk_kernel<<<dim3(S_/64, S_/64, B_*H_), dim3(256)>>>(q, k, padmask, scores);
        softmax_kernel<<<B_*H_*S_, 128>>>(scores);
        pv_kernel<<<dim3(1, S_/64, B_*H_), dim3(256)>>>(scores, v, attn);

        // x = x + attn @ Wo + bo
        gemm_tc<<<dim3(D_/TBN, T_/TBM), blk, SMEM_BYTES>>>(attn, wo, bo + l*D_,
            nullptr, nullptr, nullptr, x, x, T_, D_, D_, 0);

        ln_kernel<<<T_, 256>>>(x, ln2_g + l*D_, ln2_b + l*D_, h);

        // ff = gelu(h @ W1 + b1)
        gemm_tc<<<dim3(F_/TBN, T_/TBM), blk, SMEM_BYTES>>>(h, w1, bff1 + l*F_,
            nullptr, nullptr, nullptr, nullptr, ff, T_, F_, D_, 1);

        // x = x + ff @ W2 + b2
        gemm_tc<<<dim3(D_/TBN, T_/TBM), blk, SMEM_BYTES>>>(ff, w2, bff2 + l*D_,
            nullptr, nullptr, nullptr, x, x, T_, D_, F_, 0);
    }
}

// round 10
// speedup vs baseline: 1.7099x; 1.0084x over previous
#include <cuda_runtime.h>
#include <math.h>
#include <stdint.h>

#define L_   12
#define S_   512
#define B_   4
#define DIN_ 768
#define D_   1024
#define H_   16
#define F_   4096
#define HD_  64
#define T_   (S_*B_)   // 2048 tokens

// ---------------- scratch (static device globals; no runtime allocation) ----
__device__ float g_h[T_*D_];
__device__ float g_q[T_*D_];
__device__ float g_k[T_*D_];
__device__ float g_v[T_*D_];
__device__ float g_attn[T_*D_];
__device__ float g_ff[(size_t)T_*F_];
__device__ float g_scores[(size_t)B_*H_*S_*S_];   // 67 MB

// ---------------- bf16 split helpers ---------------------------------------
__device__ __forceinline__ unsigned pack_bf16(float x0, float x1) {
    unsigned u;
    asm("cvt.rn.bf16x2.f32 %0, %1, %2;" : "=r"(u) : "f"(x1), "f"(x0));
    return u;
}
__device__ __forceinline__ void split4_bf16(float4 v, unsigned& h0, unsigned& h1,
                                            unsigned& l0, unsigned& l1)
{
    h0 = pack_bf16(v.x, v.y);
    h1 = pack_bf16(v.z, v.w);
    const float hx = __uint_as_float(h0 << 16);
    const float hy = __uint_as_float(h0 & 0xffff0000u);
    const float hz = __uint_as_float(h1 << 16);
    const float hw = __uint_as_float(h1 & 0xffff0000u);
    l0 = pack_bf16(v.x - hx, v.y - hy);
    l1 = pack_bf16(v.z - hz, v.w - hw);
}
__device__ __forceinline__ void splitp_bf16(float a, float b, unsigned& h, unsigned& l)
{
    h = pack_bf16(a, b);
    const float ha = __uint_as_float(h << 16);
    const float hb = __uint_as_float(h & 0xffff0000u);
    l = pack_bf16(a - ha, b - hb);
}

__device__ __forceinline__ void mma_bf16(float c[4],
    unsigned a0, unsigned a1, unsigned a2, unsigned a3,
    unsigned b0, unsigned b1)
{
    asm volatile(
        "mma.sync.aligned.m16n8k16.row.col.f32.bf16.bf16.f32 "
        "{%0,%1,%2,%3}, {%4,%5,%6,%7}, {%8,%9}, {%0,%1,%2,%3};"
        : "+f"(c[0]), "+f"(c[1]), "+f"(c[2]), "+f"(c[3])
        : "r"(a0), "r"(a1), "r"(a2), "r"(a3), "r"(b0), "r"(b1));
}

// ---------------- tensor-core GEMM (3x bf16 split, frag-major A) -----------
// C = A[MxK] @ W[KxN] + bias[c] + bias2[c] + rowvec[r]*colvec[c];
// optional exact GELU; + residual[r,c]
// block tile 128x128x32, 8 warps (2x4), warp tile 64x32, m16n8k16 bf16
// smem per stage (u32): A frag-major [8 mtiles][2 steps][2 hl][32 lanes][4]
//                       = 4096 u32; B k-pair-major hi/lo [16][136] x2 = 4352
#define TBM 128
#define TBN 128
#define TBK 32
#define B_STU 136
#define AFRAG_U 4096
#define OFF_BHU AFRAG_U                        // 4096
#define OFF_BLU (AFRAG_U + 16*B_STU)           // 6272
#define STAGE_U (AFRAG_U + 2*16*B_STU)         // 8448
#define SMEM_BYTES (2*STAGE_U*4)               // 67584

// A fragment index: ((mt8*2 + step)*2 + hl)*128 + lane*4 + reg
__device__ __forceinline__ int afrag_idx(int mt8, int step, int hl, int lane) {
    return (((mt8 * 2 + step) * 2 + hl) * 128) + lane * 4;
}

__device__ __forceinline__ void store_split_tile(
    unsigned* stage, int tid, const float4* pa,
    const float4* pb0, const float4* pb1)
{
    // A: 128x32 floats -> frag-major hi/lo bf16x2
    #pragma unroll
    for (int it = 0; it < 4; it++) {
        const int s = tid + it * 256;
        const int r = s >> 3, kc = (s & 7) * 4;   // k floats kc..kc+3
        unsigned h[2], l[2];
        split4_bf16(pa[it], h[0], h[1], l[0], l[1]);
        const int rr  = r & 15;
        const int mt8 = r >> 4;
        const int P0  = kc >> 1;                  // first k-pair (even)
        #pragma unroll
        for (int j = 0; j < 2; j++) {
            const int p    = P0 + j;
            const int step = p >> 3;
            const int pp   = p & 7;
            const int lane = (rr & 7) * 4 + (pp & 3);
            const int reg  = (rr >> 3) + ((pp >> 2) << 1);
            stage[afrag_idx(mt8, step, 0, lane) + reg] = h[j];
            stage[afrag_idx(mt8, step, 1, lane) + reg] = l[j];
        }
    }
    // B: 32x128 floats -> k-pair packed hi/lo [16][136] u32
    #pragma unroll
    for (int it = 0; it < 2; it++) {
        const int s = tid + it * 256;
        const int p  = s >> 5;            // k-pair 0..15
        const int nq = (s & 31) * 4;      // n offset
        uint4 hv, lv;
        splitp_bf16(pb0[it].x, pb1[it].x, hv.x, lv.x);
        splitp_bf16(pb0[it].y, pb1[it].y, hv.y, lv.y);
        splitp_bf16(pb0[it].z, pb1[it].z, hv.z, lv.z);
        splitp_bf16(pb0[it].w, pb1[it].w, hv.w, lv.w);
        *(uint4*)&stage[OFF_BHU + p * B_STU + nq] = hv;
        *(uint4*)&stage[OFF_BLU + p * B_STU + nq] = lv;
    }
}

__global__ __launch_bounds__(256, 1) void gemm_tc(
    const float* __restrict__ A, const float* __restrict__ Bw,
    const float* __restrict__ bias, const float* __restrict__ bias2,
    const float* __restrict__ rowvec, const float* __restrict__ colvec,
    const float* __restrict__ residual,
    float* __restrict__ C, int M, int N, int K, int gelu_flag)
{
    extern __shared__ unsigned smbuf[];
    unsigned* cur = smbuf;
    unsigned* nxt = smbuf + STAGE_U;

    const int tid  = threadIdx.x;
    const int warp = tid >> 5;
    const int lane = tid & 31;
    const int g    = lane >> 2;      // 0..7
    const int tig  = lane & 3;       // 0..3
    const int wmt  = (warp >> 2) * 4;    // first m-tile of this warp (0 or 4)
    const int wm   = wmt * 16;
    const int wn   = (warp & 3) * 32;    // 0,32,64,96

    const int row0 = blockIdx.y * TBM;
    const int col0 = blockIdx.x * TBN;

    float acc[4][4][4];
    #pragma unroll
    for (int mt = 0; mt < 4; mt++)
        #pragma unroll
        for (int nt = 0; nt < 4; nt++)
            #pragma unroll
            for (int r = 0; r < 4; r++) acc[mt][nt][r] = 0.f;

    float4 pa[4], pb0[2], pb1[2];

    // ---- prologue: load tile 0 and split into cur
    #pragma unroll
    for (int it = 0; it < 4; it++) {
        const int s = tid + it * 256;
        pa[it] = *(const float4*)(A + (size_t)(row0 + (s >> 3)) * K + (s & 7) * 4);
    }
    #pragma unroll
    for (int it = 0; it < 2; it++) {
        const int s = tid + it * 256;
        const int p = s >> 5, nq = (s & 31) * 4;
        pb0[it] = *(const float4*)(Bw + (size_t)(2 * p)     * N + col0 + nq);
        pb1[it] = *(const float4*)(Bw + (size_t)(2 * p + 1) * N + col0 + nq);
    }
    store_split_tile(cur, tid, pa, pb0, pb1);
    __syncthreads();

    const int nk = K / TBK;
    for (int ki = 0; ki < nk; ki++) {
        const bool more = (ki + 1 < nk);
        if (more) {
            const int k0n = (ki + 1) * TBK;
            #pragma unroll
            for (int it = 0; it < 4; it++) {
                const int s = tid + it * 256;
                pa[it] = *(const float4*)(A + (size_t)(row0 + (s >> 3)) * K + k0n + (s & 7) * 4);
            }
            #pragma unroll
            for (int it = 0; it < 2; it++) {
                const int s = tid + it * 256;
                const int p = s >> 5, nq = (s & 31) * 4;
                pb0[it] = *(const float4*)(Bw + (size_t)(k0n + 2 * p)     * N + col0 + nq);
                pb1[it] = *(const float4*)(Bw + (size_t)(k0n + 2 * p + 1) * N + col0 + nq);
            }
        }

        // ---- compute current stage: 2 x k16 steps; A frags via LDS.128
        const unsigned* Bh = cur + OFF_BHU;
        const unsigned* Bl = cur + OFF_BLU;
        #pragma unroll
        for (int st = 0; st < 2; st++) {
            const int pb = st * 8;
            unsigned ah[4][4], al[4][4];
            #pragma unroll
            for (int mt = 0; mt < 4; mt++) {
                uint4 av = *(const uint4*)&cur[afrag_idx(wmt + mt, st, 0, lane)];
                ah[mt][0] = av.x; ah[mt][1] = av.y; ah[mt][2] = av.z; ah[mt][3] = av.w;
                uint4 lv = *(const uint4*)&cur[afrag_idx(wmt + mt, st, 1, lane)];
                al[mt][0] = lv.x; al[mt][1] = lv.y; al[mt][2] = lv.z; al[mt][3] = lv.w;
            }
            unsigned bh[4][2], bl[4][2];
            #pragma unroll
            for (int nt = 0; nt < 4; nt++) {
                const int n = wn + nt * 8 + g;
                const int c0i = (pb + tig) * B_STU + n;
                const int c1i = (pb + tig + 4) * B_STU + n;
                bh[nt][0] = Bh[c0i]; bh[nt][1] = Bh[c1i];
                bl[nt][0] = Bl[c0i]; bl[nt][1] = Bl[c1i];
            }
            #pragma unroll
            for (int mt = 0; mt < 4; mt++)
                #pragma unroll
                for (int nt = 0; nt < 4; nt++) {
                    mma_bf16(acc[mt][nt], ah[mt][0], ah[mt][1], ah[mt][2], ah[mt][3],
                             bh[nt][0], bh[nt][1]);
                    mma_bf16(acc[mt][nt], al[mt][0], al[mt][1], al[mt][2], al[mt][3],
                             bh[nt][0], bh[nt][1]);
                    mma_bf16(acc[mt][nt], ah[mt][0], ah[mt][1], ah[mt][2], ah[mt][3],
                             bl[nt][0], bl[nt][1]);
                }
        }

        if (more) store_split_tile(nxt, tid, pa, pb0, pb1);
        __syncthreads();
        unsigned* t = cur; cur = nxt; nxt = t;
    }

    // ---- epilogue
    #pragma unroll
    for (int mt = 0; mt < 4; mt++) {
        #pragma unroll
        for (int half = 0; half < 2; half++) {
            const int r = row0 + wm + mt * 16 + g + half * 8;
            const float rv = rowvec ? rowvec[r] : 0.f;
            #pragma unroll
            for (int nt = 0; nt < 4; nt++) {
                const int c = col0 + wn + nt * 8 + 2 * tig;
                float v0 = acc[mt][nt][half * 2 + 0];
                float v1 = acc[mt][nt][half * 2 + 1];
                if (bias)  { v0 += bias[c];  v1 += bias[c + 1]; }
                if (bias2) { v0 += bias2[c]; v1 += bias2[c + 1]; }
                if (rowvec) { v0 += rv * colvec[c]; v1 += rv * colvec[c + 1]; }
                if (gelu_flag) {
                    v0 = 0.5f * v0 * (1.f + erff(v0 * 0.70710678118654752f));
                    v1 = 0.5f * v1 * (1.f + erff(v1 * 0.70710678118654752f));
                }
                if (residual) {
                    float2 rr = *(const float2*)(residual + (size_t)r * N + c);
                    v0 += rr.x; v1 += rr.y;
                }
                float2 o; o.x = v0; o.y = v1;
                *(float2*)(C + (size_t)r * N + c) = o;
            }
        }
    }
}

// ---------------- LayerNorm: one block per token ---------------------------
__global__ __launch_bounds__(256) void ln_kernel(
    const float* __restrict__ x, const float* __restrict__ g,
    const float* __restrict__ bta, float* __restrict__ out)
{
    const int t = blockIdx.x;
    const int tid = threadIdx.x;
    const float* xr = x + (size_t)t * D_;

    float v[4];
    float s = 0.f, s2 = 0.f;
    #pragma unroll
    for (int i = 0; i < 4; i++) {
        v[i] = xr[tid + i*256];
        s  += v[i];
        s2 += v[i] * v[i];
    }
    #pragma unroll
    for (int o = 16; o; o >>= 1) {
        s  += __shfl_xor_sync(0xffffffffu, s,  o);
        s2 += __shfl_xor_sync(0xffffffffu, s2, o);
    }
    __shared__ float ss[8], ss2[8];
    if ((tid & 31) == 0) { ss[tid >> 5] = s; ss2[tid >> 5] = s2; }
    __syncthreads();
    s = 0.f; s2 = 0.f;
    #pragma unroll
    for (int w = 0; w < 8; w++) { s += ss[w]; s2 += ss2[w]; }

    const float mean = s * (1.f / D_);
    const float var  = s2 * (1.f / D_) - mean * mean;
    const float inv  = rsqrtf(var + 1e-5f);

    float* orow = out + (size_t)t * D_;
    #pragma unroll
    for (int i = 0; i < 4; i++) {
        const int c = tid + i*256;
        orow[c] = (v[i] - mean) * inv * g[c] + bta[c];
    }
}

// ---------------- RoPE (in-place, one thread owns the rotation pair) -------
__global__ __launch_bounds__(256) void rope_kernel(float* __restrict__ x)
{
    const int idx = blockIdx.x * 256 + threadIdx.x;
    const int j = idx & 31;
    const int h = (idx >> 5) & 15;
    const int t = idx >> 9;
    const int s = t >> 2;

    const float inv_freq = powf(10000.f, -((float)(2*j)) * (1.f / HD_));
    float sn, c;
    sincosf((float)s * inv_freq, &sn, &c);

    float* base = x + (size_t)t * D_ + h * HD_;
    const float x1 = base[j];
    const float x2 = base[j + 32];
    base[j]      = x1 * c - x2 * sn;
    base[j + 32] = x2 * c + x1 * sn;
}

// ---------------- scores = scale * Q K^T, masked ---------------------------
__global__ __launch_bounds__(256) void qk_kernel(
    const float* __restrict__ q, const float* __restrict__ k,
    const int* __restrict__ mask, float* __restrict__ scores)
{
    const int bh = blockIdx.z;
    const int b = bh >> 4;
    const int h = bh & 15;
    const int qt = blockIdx.y * 64;
    const int kt = blockIdx.x * 64;

    __shared__ float Qs[HD_][65];
    __shared__ float Ks[HD_][65];

    const int tid = threadIdx.x;
    const int ty = tid >> 4, tx = tid & 15;
    const int lr = tid >> 4;
    const int lc = (tid & 15) * 4;

    #pragma unroll
    for (int it = 0; it < 4; it++) {
        const int m = lr + it*16;
        float4 a = *(const float4*)(q + ((size_t)(qt + m) * B_ + b) * D_ + h*HD_ + lc);
        Qs[lc+0][m]=a.x; Qs[lc+1][m]=a.y; Qs[lc+2][m]=a.z; Qs[lc+3][m]=a.w;
        float4 bb = *(const float4*)(k + ((size_t)(kt + m) * B_ + b) * D_ + h*HD_ + lc);
        Ks[lc+0][m]=bb.x; Ks[lc+1][m]=bb.y; Ks[lc+2][m]=bb.z; Ks[lc+3][m]=bb.w;
    }
    __syncthreads();

    float acc[4][4];
    #pragma unroll
    for (int i = 0; i < 4; i++)
        #pragma unroll
        for (int j = 0; j < 4; j++) acc[i][j] = 0.f;

    #pragma unroll
    for (int kk = 0; kk < HD_; kk++) {
        float av[4], bv[4];
        #pragma unroll
        for (int i = 0; i < 4; i++) av[i] = Qs[kk][ty*4 + i];
        #pragma unroll
        for (int j = 0; j < 4; j++) bv[j] = Ks[kk][tx*4 + j];
        #pragma unroll
        for (int i = 0; i < 4; i++)
            #pragma unroll
            for (int j = 0; j < 4; j++)
                acc[i][j] = fmaf(av[i], bv[j], acc[i][j]);
    }

    const float scale = 0.125f;
    #pragma unroll
    for (int i = 0; i < 4; i++) {
        const int qpos = qt + ty*4 + i;
        float* out = scores + ((size_t)bh * S_ + qpos) * S_;
        #pragma unroll
        for (int j = 0; j < 4; j++) {
            const int kpos = kt + tx*4 + j;
            float vsc = acc[i][j] * scale;
            if (mask[b * S_ + kpos] != 0) vsc = -1e30f;
            out[kpos] = vsc;
        }
    }
}

// ---------------- row softmax over 512 keys --------------------------------
__global__ __launch_bounds__(128) void softmax_kernel(float* __restrict__ scores)
{
    const size_t row = blockIdx.x;
    float* p = scores + row * S_;
    const int tid = threadIdx.x;

    float vals[4];
    float m = -3.0e38f;
    #pragma unroll
    for (int i = 0; i < 4; i++) { vals[i] = p[tid + i*128]; m = fmaxf(m, vals[i]); }
    #pragma unroll
    for (int o = 16; o; o >>= 1) m = fmaxf(m, __shfl_xor_sync(0xffffffffu, m, o));
    __shared__ float sm[4], ssum[4];
    if ((tid & 31) == 0) sm[tid >> 5] = m;
    __syncthreads();
    m = fmaxf(fmaxf(sm[0], sm[1]), fmaxf(sm[2], sm[3]));

    float s = 0.f;
    #pragma unroll
    for (int i = 0; i < 4; i++) { vals[i] = __expf(vals[i] - m); s += vals[i]; }
    #pragma unroll
    for (int o = 16; o; o >>= 1) s += __shfl_xor_sync(0xffffffffu, s, o);
    if ((tid & 31) == 0) ssum[tid >> 5] = s;
    __syncthreads();
    const float inv = 1.f / (ssum[0] + ssum[1] + ssum[2] + ssum[3]);

    #pragma unroll
    for (int i = 0; i < 4; i++) p[tid + i*128] = vals[i] * inv;
}

// ---------------- attn = probs @ V, scattered to [t, d] layout -------------
__global__ __launch_bounds__(256) void pv_kernel(
    const float* __restrict__ scores, const float* __restrict__ v,
    float* __restrict__ attn)
{
    const int bh = blockIdx.z;
    const int b = bh >> 4, h = bh & 15;
    const int qt = blockIdx.y * 64;

    __shared__ float Ps[32][65];
    __shared__ float Vs[32][64];

    const int tid = threadIdx.x;
    const int ty = tid >> 4, tx = tid & 15;
    const int pr = tid >> 3;
    const int pc = (tid & 7) * 4;
    const int vr = tid >> 4;
    const int vc = (tid & 15) * 4;

    float acc[4][4];
    #pragma unroll
    for (int i = 0; i < 4; i++)
        #pragma unroll
        for (int j = 0; j < 4; j++) acc[i][j] = 0.f;

    for (int kt = 0; kt < S_; kt += 32) {
        #pragma unroll
        for (int it = 0; it < 2; it++) {
            const int m = pr + it*32;
            float4 a = *(const float4*)(scores + ((size_t)bh*S_ + qt + m)*S_ + kt + pc);
            Ps[pc+0][m]=a.x; Ps[pc+1][m]=a.y; Ps[pc+2][m]=a.z; Ps[pc+3][m]=a.w;
        }
        #pragma unroll
        for (int it = 0; it < 2; it++) {
            const int kr = vr + it*16;
            float4 bb = *(const float4*)(v + ((size_t)(kt + kr)*B_ + b)*D_ + h*HD_ + vc);
            *(float4*)&Vs[kr][vc] = bb;
        }
        __syncthreads();

        #pragma unroll
        for (int kk = 0; kk < 32; kk++) {
            float av[4], bv[4];
            #pragma unroll
            for (int i = 0; i < 4; i++) av[i] = Ps[kk][ty*4 + i];
            #pragma unroll
            for (int j = 0; j < 4; j++) bv[j] = Vs[kk][tx*4 + j];
            #pragma unroll
            for (int i = 0; i < 4; i++)
                #pragma unroll
                for (int j = 0; j < 4; j++)
                    acc[i][j] = fmaf(av[i], bv[j], acc[i][j]);
        }
        __syncthreads();
    }

    #pragma unroll
    for (int i = 0; i < 4; i++) {
        const int qpos = qt + ty*4 + i;
        float* orow = attn + ((size_t)qpos * B_ + b) * D_ + h*HD_;
        #pragma unroll
        for (int j = 0; j < 4; j++)
            orow[tx*4 + j] = acc[i][j];
    }
}

// ---------------- host orchestration ---------------------------------------
extern "C" void kernel_launch(void* const* d_in, const int* in_sizes, int n_in,
                              void* d_out, int out_size)
{
    (void)in_sizes; (void)n_in; (void)out_size;

    const float* segments  = (const float*)d_in[0];
    const float* durations = (const float*)d_in[1];
    const int*   padmask   = (const int*)d_in[2];   // bool promoted to int32
    const float* Wproj = (const float*)d_in[3];
    const float* bproj = (const float*)d_in[4];
    const float* Wdur  = (const float*)d_in[5];
    const float* bdur  = (const float*)d_in[6];
    const float* ln1_g = (const float*)d_in[7];
    const float* ln1_b = (const float*)d_in[8];
    const float* Wq = (const float*)d_in[9];
    const float* bq = (const float*)d_in[10];
    const float* Wk = (const float*)d_in[11];
    const float* bk = (const float*)d_in[12];
    const float* Wv = (const float*)d_in[13];
    const float* bv = (const float*)d_in[14];
    const float* Wo = (const float*)d_in[15];
    const float* bo = (const float*)d_in[16];
    const float* ln2_g = (const float*)d_in[17];
    const float* ln2_b = (const float*)d_in[18];
    const float* Wff1 = (const float*)d_in[19];
    const float* bff1 = (const float*)d_in[20];
    const float* Wff2 = (const float*)d_in[21];
    const float* bff2 = (const float*)d_in[22];

    float* x = (float*)d_out;

    float *h, *q, *k, *v, *attn, *ff, *scores;
    cudaGetSymbolAddress((void**)&h,      g_h);
    cudaGetSymbolAddress((void**)&q,      g_q);
    cudaGetSymbolAddress((void**)&k,      g_k);
    cudaGetSymbolAddress((void**)&v,      g_v);
    cudaGetSymbolAddress((void**)&attn,   g_attn);
    cudaGetSymbolAddress((void**)&ff,     g_ff);
    cudaGetSymbolAddress((void**)&scores, g_scores);

    cudaFuncSetAttribute(gemm_tc,
        cudaFuncAttributeMaxDynamicSharedMemorySize, SMEM_BYTES);

    const dim3 blk(256);

    // x = segments @ Wproj + bproj + durations*Wdur + bdur
    gemm_tc<<<dim3(D_/TBN, T_/TBM), blk, SMEM_BYTES>>>(
        segments, Wproj, bproj, bdur, durations, Wdur, nullptr,
        x, T_, D_, DIN_, 0);

    for (int l = 0; l < L_; l++) {
        const float* wq = Wq + (size_t)l*D_*D_;
        const float* wk = Wk + (size_t)l*D_*D_;
        const float* wv = Wv + (size_t)l*D_*D_;
        const float* wo = Wo + (size_t)l*D_*D_;
        const float* w1 = Wff1 + (size_t)l*D_*F_;
        const float* w2 = Wff2 + (size_t)l*F_*D_;

        ln_kernel<<<T_, 256>>>(x, ln1_g + l*D_, ln1_b + l*D_, h);

        gemm_tc<<<dim3(D_/TBN, T_/TBM), blk, SMEM_BYTES>>>(h, wq, bq + l*D_,
            nullptr, nullptr, nullptr, nullptr, q, T_, D_, D_, 0);
        gemm_tc<<<dim3(D_/TBN, T_/TBM), blk, SMEM_BYTES>>>(h, wk, bk + l*D_,
            nullptr, nullptr, nullptr, nullptr, k, T_, D_, D_, 0);
        gemm_tc<<<dim3(D_/TBN, T_/TBM), blk, SMEM_BYTES>>>(h, wv, bv + l*D_,
            nullptr, nullptr, nullptr, nullptr, v, T_, D_, D_, 0);

        rope_kernel<<<(T_*H_*32)/256, 256>>>(q);
        rope_kernel<<<(T_*H_*32)/256, 256>>>(k);

        qk_kernel<<<dim3(S_/64, S_/64, B_*H_), dim3(256)>>>(q, k, padmask, scores);
        softmax_kernel<<<B_*H_*S_, 128>>>(scores);
        pv_kernel<<<dim3(1, S_/64, B_*H_), dim3(256)>>>(scores, v, attn);

        // x = x + attn @ Wo + bo
        gemm_tc<<<dim3(D_/TBN, T_/TBM), blk, SMEM_BYTES>>>(attn, wo, bo + l*D_,
            nullptr, nullptr, nullptr, x, x, T_, D_, D_, 0);

        ln_kernel<<<T_, 256>>>(x, ln2_g + l*D_, ln2_b + l*D_, h);

        // ff = gelu(h @ W1 + b1)
        gemm_tc<<<dim3(F_/TBN, T_/TBM), blk, SMEM_BYTES>>>(h, w1, bff1 + l*F_,
            nullptr, nullptr, nullptr, nullptr, ff, T_, F_, D_, 1);

        // x = x + ff @ W2 + b2
        gemm_tc<<<dim3(D_/TBN, T_/TBM), blk, SMEM_BYTES>>>(ff, w2, bff2 + l*D_,
            nullptr, nullptr, nullptr, x, x, T_, D_, F_, 0);
    }
}